// round 6
// baseline (speedup 1.0000x reference)
#include <cuda_runtime.h>
#include <cstddef>

// out[b,i,f] = X[b,0,i,i,f] + sum_{k=1..3} sum_j A[b,i,j] * X[b,k,i,j,f]
// A: (4,256,256) fp32, X: (4,4,256,256,64) fp32, out: (4,256,64) fp32.
//
// L2 residency plan (126 MB L2, graph-replay steady state):
//   resident (evict-normal): hop k=1 (64 MB) + hop k=2 for b<2 (32 MB) = 96 MB
//   streaming (__ldcs evict-first): hop k=2 for b>=2 + hop k=3 (96 MB)
// Per-warp hop-order rotation (w % 3) keeps the L2-hit stream and the DRAM
// stream in flight simultaneously instead of phase-serialized.

#define BATCH 4
#define KP1   4
#define NN    256
#define FF    64   // 16 float4 per j-row

template <bool STREAM>
__device__ __forceinline__ void hop_accum(const float4* __restrict__ xp,
                                          const float* __restrict__ sA,
                                          int jg, int f4, float4& acc)
{
    #pragma unroll 4
    for (int jj = 0; jj < 16; ++jj) {
        const int   j = jj * 16 + jg;
        const float a = sA[j];
        const float4 x = STREAM ? __ldcs(&xp[(size_t)j * 16 + f4])
                                : __ldg (&xp[(size_t)j * 16 + f4]);
        acc.x += a * x.x;  acc.y += a * x.y;
        acc.z += a * x.z;  acc.w += a * x.w;
    }
}

__global__ __launch_bounds__(256, 8)
void gnn_fused_kernel(const float* __restrict__ A,
                      const float* __restrict__ X,
                      float* __restrict__ out)
{
    // One CTA per (b, i) — 1024 CTAs, single wave at occ 8.
    const int bi = blockIdx.x;
    const int b  = bi >> 8;
    const int i  = bi & 255;

    __shared__ float  sA[NN];
    __shared__ float4 sred[256];

    const int t  = threadIdx.x;      // 0..255
    const int f4 = t & 15;           // float4 slot within F
    const int jg = t >> 4;           // j-group (0..15)
    const int w  = t >> 5;           // warp id (0..7)

    sA[t] = A[(size_t)b * (NN * NN) + (size_t)i * NN + t];
    __syncthreads();

    const size_t strideK = (size_t)NN * NN * FF;
    const size_t baseBI  = (size_t)b * KP1 * strideK + (size_t)i * (NN * FF);

    const float4* __restrict__ xp1 =
        reinterpret_cast<const float4*>(X + baseBI + 1 * strideK);
    const float4* __restrict__ xp2 =
        reinterpret_cast<const float4*>(X + baseBI + 2 * strideK);
    const float4* __restrict__ xp3 =
        reinterpret_cast<const float4*>(X + baseBI + 3 * strideK);

    const bool h2_resident = (b < 2);   // CTA-uniform

    float4 acc = make_float4(0.f, 0.f, 0.f, 0.f);

    const int r = w % 3;               // warp-uniform rotation
    if (r == 0) {
        hop_accum<false>(xp1, sA, jg, f4, acc);
        if (h2_resident) hop_accum<false>(xp2, sA, jg, f4, acc);
        else             hop_accum<true >(xp2, sA, jg, f4, acc);
        hop_accum<true>(xp3, sA, jg, f4, acc);
    } else if (r == 1) {
        if (h2_resident) hop_accum<false>(xp2, sA, jg, f4, acc);
        else             hop_accum<true >(xp2, sA, jg, f4, acc);
        hop_accum<true >(xp3, sA, jg, f4, acc);
        hop_accum<false>(xp1, sA, jg, f4, acc);
    } else {
        hop_accum<true >(xp3, sA, jg, f4, acc);
        hop_accum<false>(xp1, sA, jg, f4, acc);
        if (h2_resident) hop_accum<false>(xp2, sA, jg, f4, acc);
        else             hop_accum<true >(xp2, sA, jg, f4, acc);
    }

    sred[t] = acc;
    __syncthreads();

    // 2-stage reduction over the 16 j-groups
    if (t < 64) {
        const int g  = t >> 4;
        const int ff = t & 15;
        float4 m = sred[(g * 4 + 0) * 16 + ff];
        #pragma unroll
        for (int m2 = 1; m2 < 4; ++m2) {
            const float4 o = sred[(g * 4 + m2) * 16 + ff];
            m.x += o.x; m.y += o.y; m.z += o.z; m.w += o.w;
        }
        sred[g * 16 + ff] = m;
    }
    __syncthreads();

    if (t < 16) {
        float4 m = sred[0 * 16 + t];
        #pragma unroll
        for (int g = 1; g < 4; ++g) {
            const float4 o = sred[g * 16 + t];
            m.x += o.x; m.y += o.y; m.z += o.z; m.w += o.w;
        }
        // hop-0 identity contribution: diagonal X[b,0,i,i,f]
        const float4* __restrict__ xd =
            reinterpret_cast<const float4*>(X + baseBI + (size_t)i * FF);
        const float4 d = __ldg(&xd[t]);
        m.x += d.x; m.y += d.y; m.z += d.z; m.w += d.w;
        reinterpret_cast<float4*>(out)[((size_t)b * NN + i) * 16 + t] = m;
    }
}

extern "C" void kernel_launch(void* const* d_in, const int* in_sizes, int n_in,
                              void* d_out, int out_size)
{
    const float* A;
    const float* X;
    if (in_sizes[0] == BATCH * NN * NN) {
        A = (const float*)d_in[0];
        X = (const float*)d_in[1];
    } else {
        A = (const float*)d_in[1];
        X = (const float*)d_in[0];
    }
    float* out = (float*)d_out;

    gnn_fused_kernel<<<dim3(BATCH * NN), dim3(256)>>>(A, X, out);
}